// round 12
// baseline (speedup 1.0000x reference)
#include <cuda_runtime.h>
#include <cuda_fp16.h>
#include <math.h>
#include <stdint.h>

#define NB 2
#define NL 2048
#define NS 2048
#define NH 8
#define NE 64
#define NBH 16
#define SCALE 0.125f
#define TQ 128
#define TN 64
#define NQT (NL / TQ)
#define NKT (NS / TN)

// ---------------- device scratch (single fp16 tiles) ----------------
__device__ __align__(16) uint8_t g_kf[NBH][NKT][8192];
__device__ __align__(16) uint8_t g_vf[NBH][NKT][8192];
__device__ unsigned char g_mk[NB * NS];
__device__ unsigned char g_mq[NB * NL];

// ---------------- helpers ----------------
__device__ __forceinline__ uint32_t cvt_f16x2(float hi, float lo) {
    uint32_t r;
    asm("cvt.rn.f16x2.f32 %0, %1, %2;" : "=r"(r) : "f"(hi), "f"(lo));
    return r;
}
__device__ __forceinline__ float2 unpack_f16x2(uint32_t p) {
    __half2 h = *reinterpret_cast<__half2*>(&p);
    return __half22float2(h);
}
__device__ __forceinline__ uint32_t smem_u32(const void* p) {
    uint32_t a;
    asm("{ .reg .u64 t; cvta.to.shared.u64 t, %1; cvt.u32.u64 %0, t; }" : "=r"(a) : "l"(p));
    return a;
}
__device__ __forceinline__ void mma16816(float d[4], const uint32_t a[4],
                                         uint32_t b0, uint32_t b1) {
    asm volatile(
        "mma.sync.aligned.m16n8k16.row.col.f32.f16.f16.f32 "
        "{%0,%1,%2,%3},{%4,%5,%6,%7},{%8,%9},{%0,%1,%2,%3};"
        : "+f"(d[0]), "+f"(d[1]), "+f"(d[2]), "+f"(d[3])
        : "r"(a[0]), "r"(a[1]), "r"(a[2]), "r"(a[3]), "r"(b0), "r"(b1));
}
__device__ __forceinline__ void cpa16(uint32_t dst, const void* src) {
    asm volatile("cp.async.cg.shared.global [%0], [%1], 16;" :: "r"(dst), "l"(src));
}
#define CPA_COMMIT() asm volatile("cp.async.commit_group;" ::: "memory")
#define CPA_WAIT0()  asm volatile("cp.async.wait_group 0;" ::: "memory")
#define CPA_WAIT1()  asm volatile("cp.async.wait_group 1;" ::: "memory")

// ---------------- prep: fp16 fragment tiles + mask normalization ----------------
__global__ __launch_bounds__(256) void prep_kernel(const float* __restrict__ k,
                                                   const float* __restrict__ v,
                                                   const void* mk_raw,
                                                   const void* mq_raw) {
    if (blockIdx.x >= 2048) {
        __shared__ int sh_f32, sh_u8;
        if (threadIdx.x == 0) { sh_f32 = 0; sh_u8 = 0; }
        __syncthreads();
        const uint32_t* p32 = (const uint32_t*)mk_raw;
        int f32 = 0, u8 = 0;
        #pragma unroll
        for (int it = 0; it < 4; it++) {
            uint32_t wv = p32[it * 256 + threadIdx.x];
            if (((wv >> 24) & 0xff) == 0x3f) f32 = 1;
            if (wv & 0x00ffff00u) u8 = 1;
        }
        if (f32) atomicOr(&sh_f32, 1);
        if (u8) atomicOr(&sh_u8, 1);
        __syncthreads();
        int mode = sh_f32 ? 2 : (sh_u8 ? 1 : 0);
        int idx = (blockIdx.x - 2048) * 256 + threadIdx.x;
        unsigned char vk, vq;
        if (mode == 2) { vk = ((const float*)mk_raw)[idx] != 0.0f; vq = ((const float*)mq_raw)[idx] != 0.0f; }
        else if (mode == 1) { vk = ((const unsigned char*)mk_raw)[idx] != 0; vq = ((const unsigned char*)mq_raw)[idx] != 0; }
        else { vk = ((const int*)mk_raw)[idx] != 0; vq = ((const int*)mq_raw)[idx] != 0; }
        g_mk[idx] = vk;
        g_mq[idx] = vq;
        return;
    }

    const int kind = blockIdx.x >> 10;                   // 0 = K, 1 = V^T
    const int c = ((blockIdx.x & 1023) << 8) + threadIdx.x;
    const int lane = c & 31;
    const int chunk = (c >> 5) & 1;
    const int bn = (c >> 6) & 7;
    const int kt = (c >> 9) & 31;
    const int bh = c >> 14;
    const int b = bh >> 3, h = bh & 7;
    const int c2 = lane & 3, trow = lane >> 2;

    uint32_t hp[4];
    if (kind == 0) {
        const int j = kt * 64 + bn * 8 + trow;
        const float* base = k + ((size_t)(b * NS + j) * NH + h) * NE;
        #pragma unroll
        for (int kc_in = 0; kc_in < 2; kc_in++) {
            #pragma unroll
            for (int kh = 0; kh < 2; kh++) {
                int e = (chunk * 2 + kc_in) * 16 + kh * 8 + 2 * c2;
                float2 x = *(const float2*)(base + e);
                hp[kc_in * 2 + kh] = cvt_f16x2(x.y, x.x);
            }
        }
        uint32_t off = bn * 1024 + chunk * 512 + lane * 16;
        *(uint4*)(&g_kf[bh][kt][off]) = make_uint4(hp[0], hp[1], hp[2], hp[3]);
    } else {
        const int e = bn * 8 + trow;
        #pragma unroll
        for (int kc_in = 0; kc_in < 2; kc_in++) {
            #pragma unroll
            for (int kh = 0; kh < 2; kh++) {
                int jb = kt * 64 + (chunk * 2 + kc_in) * 16 + kh * 8 + 2 * c2;
                float x0 = v[((size_t)(b * NS + jb) * NH + h) * NE + e];
                float x1 = v[((size_t)(b * NS + jb + 1) * NH + h) * NE + e];
                hp[kc_in * 2 + kh] = cvt_f16x2(x1, x0);
            }
        }
        uint32_t off = bn * 1024 + chunk * 512 + lane * 16;
        *(uint4*)(&g_vf[bh][kt][off]) = make_uint4(hp[0], hp[1], hp[2], hp[3]);
    }
}

// ---------------- attention: 2-pass fp16 flash, 2 CTAs/SM ----------------
#define SM_BYTES (32768 + 256)

__global__ __launch_bounds__(256, 2) void attn_mma_kernel(const float* __restrict__ q,
                                                          float* __restrict__ outV,
                                                          float* __restrict__ outA,
                                                          float* __restrict__ outE) {
    extern __shared__ __align__(16) char sm[];
    const int tid = threadIdx.x;
    const int w = tid >> 5;
    const int lane = tid & 31;
    const int c2 = lane & 3, trow = lane >> 2;

    const int qt = (NQT - 1) - (blockIdx.x >> 4);
    const int bh = blockIdx.x & 15;
    const int b = bh >> 3, h = bh & 7;
    const int i0 = qt * TQ;
    const int nk = 2 * qt + 2;

    const int i_r0 = i0 + w * 16 + trow;
    const int i_r1 = i_r0 + 8;
    const int i_wmax = i0 + w * 16 + 15;

    const uint32_t smb = smem_u32(sm);

    // Q-hi fragments only (ql deferred to pass 2); SCALE pre-folded
    uint32_t qh[4][4];
    {
        const float* q0 = q + ((size_t)(b * NL + i_r0) * NH + h) * NE;
        const float* q1 = q + ((size_t)(b * NL + i_r1) * NH + h) * NE;
        #pragma unroll
        for (int kc = 0; kc < 4; kc++) {
            int e = kc * 16 + 2 * c2;
            float2 a0 = *(const float2*)(q0 + e);
            float2 a1 = *(const float2*)(q1 + e);
            float2 b0 = *(const float2*)(q0 + e + 8);
            float2 b1 = *(const float2*)(q1 + e + 8);
            qh[kc][0] = cvt_f16x2(a0.y * SCALE, a0.x * SCALE);
            qh[kc][1] = cvt_f16x2(a1.y * SCALE, a1.x * SCALE);
            qh[kc][2] = cvt_f16x2(b0.y * SCALE, b0.x * SCALE);
            qh[kc][3] = cvt_f16x2(b1.y * SCALE, b1.x * SCALE);
        }
    }

    float oacc[8][4];
    #pragma unroll
    for (int bn = 0; bn < 8; bn++)
        #pragma unroll
        for (int u = 0; u < 4; u++) oacc[bn][u] = 0.0f;

    float lsum0 = 0.0f, lsum1 = 0.0f, esum0 = 0.0f, esum1 = 0.0f;
    float* Arow0 = outA + ((size_t)bh * NL + i_r0) * NS;
    float* Arow1 = outA + ((size_t)bh * NL + i_r1) * NS;

    auto stageKV = [&](int bufid, int kt) {
        const char* srcK = (const char*)g_kf[bh][kt];
        const char* srcV = (const char*)g_vf[bh][kt];
        uint32_t dst = smb + bufid * 16384;
        #pragma unroll
        for (int i = 0; i < 2; i++) {
            uint32_t off = (uint32_t)(i * 256 + tid) * 16;
            cpa16(dst + off, srcK + off);
            cpa16(dst + 8192 + off, srcV + off);
        }
        if (tid < 16)
            *(uint32_t*)(sm + 32768 + bufid * 64 + tid * 4) =
                *(const uint32_t*)(g_mk + b * NS + kt * 64 + tid * 4);
    };
    auto stageK = [&](int bufid, int kt) {
        const char* srcK = (const char*)g_kf[bh][kt];
        uint32_t dst = smb + bufid * 16384;
        #pragma unroll
        for (int i = 0; i < 2; i++) {
            uint32_t off = (uint32_t)(i * 256 + tid) * 16;
            cpa16(dst + off, srcK + off);
        }
        if (tid < 16)
            *(uint32_t*)(sm + 32768 + bufid * 64 + tid * 4) =
                *(const uint32_t*)(g_mk + b * NS + kt * 64 + tid * 4);
    };

    // ================= PASS 1: lsum/esum + AV (Q-hi only) =================
    stageKV(0, 0);
    CPA_COMMIT();

    int buf = 0;
    for (int kt = 0; kt < nk; kt++) {
        if (kt + 1 < nk) { stageKV(buf ^ 1, kt + 1); CPA_COMMIT(); CPA_WAIT1(); }
        else CPA_WAIT0();
        __syncthreads();

        const int j0 = kt * TN;
        if (j0 <= i_wmax) {
            const char* bufp = sm + buf * 16384;
            const unsigned char* msk = (const unsigned char*)(sm + 32768 + buf * 64);

            // ---- QK + epilogue per bn (local sacc, low reg pressure) ----
            uint32_t pa_hi[4][4];
            #pragma unroll
            for (int bn = 0; bn < 8; bn++) {
                uint4 h0 = *(const uint4*)(bufp + bn * 1024 + lane * 16);
                uint4 h1 = *(const uint4*)(bufp + bn * 1024 + 512 + lane * 16);
                float sacc[4] = {0.0f, 0.0f, 0.0f, 0.0f};
                mma16816(sacc, qh[0], h0.x, h0.y);
                mma16816(sacc, qh[1], h0.z, h0.w);
                mma16816(sacc, qh[2], h1.x, h1.y);
                mma16816(sacc, qh[3], h1.z, h1.w);

                int colb = j0 + bn * 8 + 2 * c2;
                unsigned char m0 = msk[bn * 8 + 2 * c2];
                unsigned char m1 = msk[bn * 8 + 2 * c2 + 1];
                float e00 = (m0 || colb > i_r0) ? 0.0f : __expf(sacc[0]);
                float e01 = (m1 || colb + 1 > i_r0) ? 0.0f : __expf(sacc[1]);
                float e10 = (m0 || colb > i_r1) ? 0.0f : __expf(sacc[2]);
                float e11 = (m1 || colb + 1 > i_r1) ? 0.0f : __expf(sacc[3]);
                lsum0 += e00 + e01; esum0 += e00 * sacc[0] + e01 * sacc[1];
                lsum1 += e10 + e11; esum1 += e10 * sacc[2] + e11 * sacc[3];
                int kc = bn >> 1, s0i = (bn & 1) * 2;
                pa_hi[kc][s0i + 0] = cvt_f16x2(e01, e00);
                pa_hi[kc][s0i + 1] = cvt_f16x2(e11, e10);
            }

            // ---- AV: single-pass (Phi) ----
            #pragma unroll
            for (int bn = 0; bn < 8; bn++) {
                uint4 h0 = *(const uint4*)(bufp + 8192 + bn * 1024 + lane * 16);
                uint4 h1 = *(const uint4*)(bufp + 8192 + bn * 1024 + 512 + lane * 16);
                mma16816(oacc[bn], pa_hi[0], h0.x, h0.y);
                mma16816(oacc[bn], pa_hi[1], h0.z, h0.w);
                mma16816(oacc[bn], pa_hi[2], h1.x, h1.y);
                mma16816(oacc[bn], pa_hi[3], h1.z, h1.w);
            }
        }
        buf ^= 1;
        __syncthreads();
    }

    // ---- stats: quad reduce, V write, entropy ----
    lsum0 += __shfl_xor_sync(0xffffffffu, lsum0, 1);
    lsum0 += __shfl_xor_sync(0xffffffffu, lsum0, 2);
    lsum1 += __shfl_xor_sync(0xffffffffu, lsum1, 1);
    lsum1 += __shfl_xor_sync(0xffffffffu, lsum1, 2);
    esum0 += __shfl_xor_sync(0xffffffffu, esum0, 1);
    esum0 += __shfl_xor_sync(0xffffffffu, esum0, 2);
    esum1 += __shfl_xor_sync(0xffffffffu, esum1, 1);
    esum1 += __shfl_xor_sync(0xffffffffu, esum1, 2);

    const bool mq0 = g_mq[b * NL + i_r0] != 0;
    const bool mq1 = g_mq[b * NL + i_r1] != 0;
    const float inv0 = mq0 ? 0.0f : 1.0f / lsum0;
    const float inv1 = mq1 ? 0.0f : 1.0f / lsum1;
    const float ls0 = __logf(inv0);     // -inf if masked -> exp() = 0
    const float ls1 = __logf(inv1);

    {
        float* vo0 = outV + ((size_t)(b * NL + i_r0) * NH + h) * NE;
        float* vo1 = outV + ((size_t)(b * NL + i_r1) * NH + h) * NE;
        #pragma unroll
        for (int bn = 0; bn < 8; bn++) {
            int e0 = bn * 8 + 2 * c2;
            *(float2*)(vo0 + e0) = make_float2(oacc[bn][0] * inv0, oacc[bn][1] * inv0);
            *(float2*)(vo1 + e0) = make_float2(oacc[bn][2] * inv1, oacc[bn][3] * inv1);
        }
    }
    if (c2 == 0) {
        outE[bh * NL + i_r0] = mq0 ? 0.0f : (__logf(lsum0) - esum0 / lsum0);
        outE[bh * NL + i_r1] = mq1 ? 0.0f : (__logf(lsum1) - esum1 / lsum1);
    }

    const float4 z4 = make_float4(0, 0, 0, 0);

    // ---- column tail zero-fill (j >= nk*64) ----
    {
        const int nk16 = nk * 16;
        #pragma unroll 1
        for (int rr = 0; rr < 16; rr++) {
            const int row = i0 + w * 16 + rr;
            float4* Ar = (float4*)(outA + ((size_t)bh * NL + row) * NS);
            for (int c4 = nk16 + lane; c4 < NS / 4; c4 += 32)
                Ar[c4] = z4;
        }
    }

    // ---- rebuild Q-lo fragments for pass 2 (deferred to cut pass-1 regs) ----
    uint32_t ql[4][4];
    {
        const float* q0 = q + ((size_t)(b * NL + i_r0) * NH + h) * NE;
        const float* q1 = q + ((size_t)(b * NL + i_r1) * NH + h) * NE;
        #pragma unroll
        for (int kc = 0; kc < 4; kc++) {
            int e = kc * 16 + 2 * c2;
            float2 a0 = *(const float2*)(q0 + e);
            float2 a1 = *(const float2*)(q1 + e);
            float2 b0 = *(const float2*)(q0 + e + 8);
            float2 b1 = *(const float2*)(q1 + e + 8);
            float2 f0 = unpack_f16x2(qh[kc][0]);
            float2 f1 = unpack_f16x2(qh[kc][1]);
            float2 f2 = unpack_f16x2(qh[kc][2]);
            float2 f3 = unpack_f16x2(qh[kc][3]);
            ql[kc][0] = cvt_f16x2(a0.y * SCALE - f0.y, a0.x * SCALE - f0.x);
            ql[kc][1] = cvt_f16x2(a1.y * SCALE - f1.y, a1.x * SCALE - f1.x);
            ql[kc][2] = cvt_f16x2(b0.y * SCALE - f2.y, b0.x * SCALE - f2.x);
            ql[kc][3] = cvt_f16x2(b1.y * SCALE - f3.y, b1.x * SCALE - f3.x);
        }
    }

    // ================= PASS 2: full-precision QK, write normalized A =================
    __syncthreads();
    stageK(0, 0);
    CPA_COMMIT();

    buf = 0;
    for (int kt = 0; kt < nk; kt++) {
        if (kt + 1 < nk) { stageK(buf ^ 1, kt + 1); CPA_COMMIT(); CPA_WAIT1(); }
        else CPA_WAIT0();
        __syncthreads();

        const int j0 = kt * TN;
        if (j0 <= i_wmax) {
            const char* bufp = sm + buf * 16384;
            const unsigned char* msk = (const unsigned char*)(sm + 32768 + buf * 64);

            #pragma unroll
            for (int bn = 0; bn < 8; bn++) {
                uint4 h0 = *(const uint4*)(bufp + bn * 1024 + lane * 16);
                uint4 h1 = *(const uint4*)(bufp + bn * 1024 + 512 + lane * 16);
                float sacc[4] = {0.0f, 0.0f, 0.0f, 0.0f};
                mma16816(sacc, qh[0], h0.x, h0.y);
                mma16816(sacc, qh[1], h0.z, h0.w);
                mma16816(sacc, qh[2], h1.x, h1.y);
                mma16816(sacc, qh[3], h1.z, h1.w);
                mma16816(sacc, ql[0], h0.x, h0.y);
                mma16816(sacc, ql[1], h0.z, h0.w);
                mma16816(sacc, ql[2], h1.x, h1.y);
                mma16816(sacc, ql[3], h1.z, h1.w);

                int colb = j0 + bn * 8 + 2 * c2;
                unsigned char m0 = msk[bn * 8 + 2 * c2];
                unsigned char m1 = msk[bn * 8 + 2 * c2 + 1];
                float a00 = (m0 || colb > i_r0) ? 0.0f : __expf(sacc[0] + ls0);
                float a01 = (m1 || colb + 1 > i_r0) ? 0.0f : __expf(sacc[1] + ls0);
                float a10 = (m0 || colb > i_r1) ? 0.0f : __expf(sacc[2] + ls1);
                float a11 = (m1 || colb + 1 > i_r1) ? 0.0f : __expf(sacc[3] + ls1);
                *(float2*)(Arow0 + colb) = make_float2(a00, a01);
                *(float2*)(Arow1 + colb) = make_float2(a10, a11);
            }
        } else {
            // above-diagonal warp tile: zeros
            #pragma unroll
            for (int rr = 0; rr < 2; rr++) {
                float* Ar = (rr == 0 ? Arow0 : Arow1) + j0;
                #pragma unroll
                for (int u = 0; u < 4; u++)
                    ((float4*)Ar)[c2 * 4 + u] = z4;
            }
        }
        buf ^= 1;
        __syncthreads();
    }
}

extern "C" void kernel_launch(void* const* d_in, const int* in_sizes, int n_in,
                              void* d_out, int out_size) {
    const float* q = (const float*)d_in[0];
    const float* k = (const float*)d_in[1];
    const float* v = (const float*)d_in[2];
    const void* mk = d_in[3];
    const void* mq = d_in[4];

    float* outV = (float*)d_out;
    float* outA = outV + (size_t)NB * NL * NH * NE;
    float* outE = outA + (size_t)NB * NH * NL * NS;

    cudaFuncSetAttribute(attn_mma_kernel,
                         cudaFuncAttributeMaxDynamicSharedMemorySize, SM_BYTES);

    prep_kernel<<<2064, 256>>>(k, v, mk, mq);
    attn_mma_kernel<<<NBH * NQT, 256, SM_BYTES>>>(q, outV, outA, outE);
}

// round 13
// speedup vs baseline: 1.1559x; 1.1559x over previous
#include <cuda_runtime.h>
#include <cuda_fp16.h>
#include <math.h>
#include <stdint.h>

#define NB 2
#define NL 2048
#define NS 2048
#define NH 8
#define NE 64
#define NBH 16
#define SCALE 0.125f
#define TQ 128
#define TN 64
#define NQT (NL / TQ)
#define NKT (NS / TN)
#define THREADS 512

// smem map
#define SM_MSK   32768               // 2 x 64B mask slots
#define SM_LS    (32768 + 128)       // lsum halves [2][128] floats
#define SM_ES    (SM_LS + 1024)      // esum halves [2][128]
#define SM_LSR   (SM_ES + 1024)      // log(inv) per row [128]
#define SM_INV   (SM_LSR + 512)      // inv per row [128]
#define SM_BYTES (SM_INV + 512)

// ---------------- device scratch (single fp16 tiles) ----------------
__device__ __align__(16) uint8_t g_kf[NBH][NKT][8192];
__device__ __align__(16) uint8_t g_vf[NBH][NKT][8192];
__device__ unsigned char g_mk[NB * NS];
__device__ unsigned char g_mq[NB * NL];

// ---------------- helpers ----------------
__device__ __forceinline__ uint32_t cvt_f16x2(float hi, float lo) {
    uint32_t r;
    asm("cvt.rn.f16x2.f32 %0, %1, %2;" : "=r"(r) : "f"(hi), "f"(lo));
    return r;
}
__device__ __forceinline__ float2 unpack_f16x2(uint32_t p) {
    __half2 h = *reinterpret_cast<__half2*>(&p);
    return __half22float2(h);
}
__device__ __forceinline__ uint32_t smem_u32(const void* p) {
    uint32_t a;
    asm("{ .reg .u64 t; cvta.to.shared.u64 t, %1; cvt.u32.u64 %0, t; }" : "=r"(a) : "l"(p));
    return a;
}
__device__ __forceinline__ void mma16816(float d[4], const uint32_t a[4],
                                         uint32_t b0, uint32_t b1) {
    asm volatile(
        "mma.sync.aligned.m16n8k16.row.col.f32.f16.f16.f32 "
        "{%0,%1,%2,%3},{%4,%5,%6,%7},{%8,%9},{%0,%1,%2,%3};"
        : "+f"(d[0]), "+f"(d[1]), "+f"(d[2]), "+f"(d[3])
        : "r"(a[0]), "r"(a[1]), "r"(a[2]), "r"(a[3]), "r"(b0), "r"(b1));
}
__device__ __forceinline__ void cpa16(uint32_t dst, const void* src) {
    asm volatile("cp.async.cg.shared.global [%0], [%1], 16;" :: "r"(dst), "l"(src));
}
#define CPA_COMMIT() asm volatile("cp.async.commit_group;" ::: "memory")
#define CPA_WAIT0()  asm volatile("cp.async.wait_group 0;" ::: "memory")
#define CPA_WAIT1()  asm volatile("cp.async.wait_group 1;" ::: "memory")

// ---------------- prep: fp16 fragment tiles + mask normalization ----------------
__global__ __launch_bounds__(256) void prep_kernel(const float* __restrict__ k,
                                                   const float* __restrict__ v,
                                                   const void* mk_raw,
                                                   const void* mq_raw) {
    if (blockIdx.x >= 2048) {
        __shared__ int sh_f32, sh_u8;
        if (threadIdx.x == 0) { sh_f32 = 0; sh_u8 = 0; }
        __syncthreads();
        const uint32_t* p32 = (const uint32_t*)mk_raw;
        int f32 = 0, u8 = 0;
        #pragma unroll
        for (int it = 0; it < 4; it++) {
            uint32_t wv = p32[it * 256 + threadIdx.x];
            if (((wv >> 24) & 0xff) == 0x3f) f32 = 1;
            if (wv & 0x00ffff00u) u8 = 1;
        }
        if (f32) atomicOr(&sh_f32, 1);
        if (u8) atomicOr(&sh_u8, 1);
        __syncthreads();
        int mode = sh_f32 ? 2 : (sh_u8 ? 1 : 0);
        int idx = (blockIdx.x - 2048) * 256 + threadIdx.x;
        unsigned char vk, vq;
        if (mode == 2) { vk = ((const float*)mk_raw)[idx] != 0.0f; vq = ((const float*)mq_raw)[idx] != 0.0f; }
        else if (mode == 1) { vk = ((const unsigned char*)mk_raw)[idx] != 0; vq = ((const unsigned char*)mq_raw)[idx] != 0; }
        else { vk = ((const int*)mk_raw)[idx] != 0; vq = ((const int*)mq_raw)[idx] != 0; }
        g_mk[idx] = vk;
        g_mq[idx] = vq;
        return;
    }

    const int kind = blockIdx.x >> 10;                   // 0 = K, 1 = V^T
    const int c = ((blockIdx.x & 1023) << 8) + threadIdx.x;
    const int lane = c & 31;
    const int chunk = (c >> 5) & 1;
    const int bn = (c >> 6) & 7;
    const int kt = (c >> 9) & 31;
    const int bh = c >> 14;
    const int b = bh >> 3, h = bh & 7;
    const int c2 = lane & 3, trow = lane >> 2;

    uint32_t hp[4];
    if (kind == 0) {
        const int j = kt * 64 + bn * 8 + trow;
        const float* base = k + ((size_t)(b * NS + j) * NH + h) * NE;
        #pragma unroll
        for (int kc_in = 0; kc_in < 2; kc_in++) {
            #pragma unroll
            for (int kh = 0; kh < 2; kh++) {
                int e = (chunk * 2 + kc_in) * 16 + kh * 8 + 2 * c2;
                float2 x = *(const float2*)(base + e);
                hp[kc_in * 2 + kh] = cvt_f16x2(x.y, x.x);
            }
        }
        uint32_t off = bn * 1024 + chunk * 512 + lane * 16;
        *(uint4*)(&g_kf[bh][kt][off]) = make_uint4(hp[0], hp[1], hp[2], hp[3]);
    } else {
        const int e = bn * 8 + trow;
        #pragma unroll
        for (int kc_in = 0; kc_in < 2; kc_in++) {
            #pragma unroll
            for (int kh = 0; kh < 2; kh++) {
                int jb = kt * 64 + (chunk * 2 + kc_in) * 16 + kh * 8 + 2 * c2;
                float x0 = v[((size_t)(b * NS + jb) * NH + h) * NE + e];
                float x1 = v[((size_t)(b * NS + jb + 1) * NH + h) * NE + e];
                hp[kc_in * 2 + kh] = cvt_f16x2(x1, x0);
            }
        }
        uint32_t off = bn * 1024 + chunk * 512 + lane * 16;
        *(uint4*)(&g_vf[bh][kt][off]) = make_uint4(hp[0], hp[1], hp[2], hp[3]);
    }
}

// ---------------- attention: 512-thread split-N flash ----------------
// warp pair (wq, wh): wq = row slab (m16), wh = key-column half of each tile.
__global__ __launch_bounds__(THREADS, 1) void attn_mma_kernel(const float* __restrict__ q,
                                                              float* __restrict__ outV,
                                                              float* __restrict__ outA,
                                                              float* __restrict__ outE) {
    extern __shared__ __align__(16) char sm[];
    const int tid = threadIdx.x;
    const int w = tid >> 5;
    const int lane = tid & 31;
    const int c2 = lane & 3, trow = lane >> 2;
    const int wq = w >> 1, wh = w & 1;

    const int qt = (NQT - 1) - (blockIdx.x >> 4);
    const int bh = blockIdx.x & 15;
    const int b = bh >> 3, h = bh & 7;
    const int i0 = qt * TQ;
    const int nk = 2 * qt + 2;

    const int i_r0 = i0 + wq * 16 + trow;
    const int i_r1 = i_r0 + 8;
    const int i_wmax = i0 + wq * 16 + 15;

    const uint32_t smb = smem_u32(sm);

    // Q-hi fragments (SCALE folded); ql deferred to pass 2
    uint32_t qh[4][4];
    {
        const float* q0 = q + ((size_t)(b * NL + i_r0) * NH + h) * NE;
        const float* q1 = q + ((size_t)(b * NL + i_r1) * NH + h) * NE;
        #pragma unroll
        for (int kc = 0; kc < 4; kc++) {
            int e = kc * 16 + 2 * c2;
            float2 a0 = *(const float2*)(q0 + e);
            float2 a1 = *(const float2*)(q1 + e);
            float2 b0 = *(const float2*)(q0 + e + 8);
            float2 b1 = *(const float2*)(q1 + e + 8);
            qh[kc][0] = cvt_f16x2(a0.y * SCALE, a0.x * SCALE);
            qh[kc][1] = cvt_f16x2(a1.y * SCALE, a1.x * SCALE);
            qh[kc][2] = cvt_f16x2(b0.y * SCALE, b0.x * SCALE);
            qh[kc][3] = cvt_f16x2(b1.y * SCALE, b1.x * SCALE);
        }
    }

    float oacc[8][4];
    #pragma unroll
    for (int bn = 0; bn < 8; bn++)
        #pragma unroll
        for (int u = 0; u < 4; u++) oacc[bn][u] = 0.0f;

    float lsum0 = 0.0f, lsum1 = 0.0f, esum0 = 0.0f, esum1 = 0.0f;
    float* Arow0 = outA + ((size_t)bh * NL + i_r0) * NS;
    float* Arow1 = outA + ((size_t)bh * NL + i_r1) * NS;

    auto stageKV = [&](int bufid, int kt) {
        uint32_t dst = smb + bufid * 16384;
        uint32_t off = (uint32_t)tid * 16;
        cpa16(dst + off, (const char*)g_kf[bh][kt] + off);
        cpa16(dst + 8192 + off, (const char*)g_vf[bh][kt] + off);
        if (tid < 16)
            *(uint32_t*)(sm + SM_MSK + bufid * 64 + tid * 4) =
                *(const uint32_t*)(g_mk + b * NS + kt * 64 + tid * 4);
    };
    auto stageK = [&](int bufid, int kt) {
        uint32_t dst = smb + bufid * 16384;
        uint32_t off = (uint32_t)tid * 16;
        cpa16(dst + off, (const char*)g_kf[bh][kt] + off);
        if (tid < 16)
            *(uint32_t*)(sm + SM_MSK + bufid * 64 + tid * 4) =
                *(const uint32_t*)(g_mk + b * NS + kt * 64 + tid * 4);
    };

    // ================= PASS 1: stats + partial AV (warp's 32-col half) =================
    stageKV(0, 0);
    CPA_COMMIT();

    int buf = 0;
    for (int kt = 0; kt < nk; kt++) {
        if (kt + 1 < nk) { stageKV(buf ^ 1, kt + 1); CPA_COMMIT(); CPA_WAIT1(); }
        else CPA_WAIT0();
        __syncthreads();

        const int j0 = kt * TN;
        if (j0 <= i_wmax) {
            const char* bufp = sm + buf * 16384;
            const unsigned char* msk = (const unsigned char*)(sm + SM_MSK + buf * 64);

            // ---- QK on this warp's 4 bn (4 independent chains) ----
            uint4 hk[4][2];
            #pragma unroll
            for (int bl = 0; bl < 4; bl++) {
                int bn = wh * 4 + bl;
                hk[bl][0] = *(const uint4*)(bufp + bn * 1024 + lane * 16);
                hk[bl][1] = *(const uint4*)(bufp + bn * 1024 + 512 + lane * 16);
            }
            float sacc[4][4];
            #pragma unroll
            for (int bl = 0; bl < 4; bl++) {
                sacc[bl][0] = 0.0f; sacc[bl][1] = 0.0f;
                sacc[bl][2] = 0.0f; sacc[bl][3] = 0.0f;
            }
            #pragma unroll
            for (int bl = 0; bl < 4; bl++) {
                mma16816(sacc[bl], qh[0], hk[bl][0].x, hk[bl][0].y);
                mma16816(sacc[bl], qh[1], hk[bl][0].z, hk[bl][0].w);
                mma16816(sacc[bl], qh[2], hk[bl][1].x, hk[bl][1].y);
                mma16816(sacc[bl], qh[3], hk[bl][1].z, hk[bl][1].w);
            }

            // ---- epilogue ----
            uint32_t pa[2][4];
            #pragma unroll
            for (int bl = 0; bl < 4; bl++) {
                int bn = wh * 4 + bl;
                int colb = j0 + bn * 8 + 2 * c2;
                unsigned char m0 = msk[bn * 8 + 2 * c2];
                unsigned char m1 = msk[bn * 8 + 2 * c2 + 1];
                float e00 = (m0 || colb > i_r0) ? 0.0f : __expf(sacc[bl][0]);
                float e01 = (m1 || colb + 1 > i_r0) ? 0.0f : __expf(sacc[bl][1]);
                float e10 = (m0 || colb > i_r1) ? 0.0f : __expf(sacc[bl][2]);
                float e11 = (m1 || colb + 1 > i_r1) ? 0.0f : __expf(sacc[bl][3]);
                lsum0 += e00 + e01; esum0 += e00 * sacc[bl][0] + e01 * sacc[bl][1];
                lsum1 += e10 + e11; esum1 += e10 * sacc[bl][2] + e11 * sacc[bl][3];
                pa[bl >> 1][(bl & 1) * 2 + 0] = cvt_f16x2(e01, e00);
                pa[bl >> 1][(bl & 1) * 2 + 1] = cvt_f16x2(e11, e10);
            }

            // ---- AV over warp's j-half (chunk wh), 8 oacc chains ----
            #pragma unroll
            for (int bn = 0; bn < 8; bn++) {
                uint4 hv = *(const uint4*)(bufp + 8192 + bn * 1024 + wh * 512 + lane * 16);
                mma16816(oacc[bn], pa[0], hv.x, hv.y);
                mma16816(oacc[bn], pa[1], hv.z, hv.w);
            }
        }
        buf ^= 1;
        __syncthreads();
    }

    // ---- quad reduce partial sums ----
    lsum0 += __shfl_xor_sync(0xffffffffu, lsum0, 1);
    lsum0 += __shfl_xor_sync(0xffffffffu, lsum0, 2);
    lsum1 += __shfl_xor_sync(0xffffffffu, lsum1, 1);
    lsum1 += __shfl_xor_sync(0xffffffffu, lsum1, 2);
    esum0 += __shfl_xor_sync(0xffffffffu, esum0, 1);
    esum0 += __shfl_xor_sync(0xffffffffu, esum0, 2);
    esum1 += __shfl_xor_sync(0xffffffffu, esum1, 1);
    esum1 += __shfl_xor_sync(0xffffffffu, esum1, 2);

    __syncthreads();   // tile buffers now free for oacc exchange

    // wh=1 warps park their partial O in the tile region
    if (wh) {
        float* dst = (float*)sm + ((size_t)wq * 32 + lane) * 32;
        #pragma unroll
        for (int bn = 0; bn < 8; bn++) {
            #pragma unroll
            for (int u = 0; u < 4; u++) dst[bn * 4 + u] = oacc[bn][u];
        }
    }
    if (c2 == 0) {
        int r0 = wq * 16 + trow;
        ((float*)(sm + SM_LS))[wh * 128 + r0] = lsum0;
        ((float*)(sm + SM_LS))[wh * 128 + r0 + 8] = lsum1;
        ((float*)(sm + SM_ES))[wh * 128 + r0] = esum0;
        ((float*)(sm + SM_ES))[wh * 128 + r0 + 8] = esum1;
    }
    __syncthreads();

    // per-row finalize: l, entropy, inv, log(inv)
    if (tid < 128) {
        float l = ((float*)(sm + SM_LS))[tid] + ((float*)(sm + SM_LS))[128 + tid];
        float e = ((float*)(sm + SM_ES))[tid] + ((float*)(sm + SM_ES))[128 + tid];
        bool mq = g_mq[b * NL + i0 + tid] != 0;
        float inv = mq ? 0.0f : 1.0f / l;
        outE[bh * NL + i0 + tid] = mq ? 0.0f : (__logf(l) - e / l);
        ((float*)(sm + SM_INV))[tid] = inv;
        ((float*)(sm + SM_LSR))[tid] = __logf(inv);   // -inf if masked
    }
    __syncthreads();

    // wh=0 warps: combine partner O, write V
    if (!wh) {
        const float* src = (const float*)sm + ((size_t)wq * 32 + lane) * 32;
        const float inv0 = ((const float*)(sm + SM_INV))[wq * 16 + trow];
        const float inv1 = ((const float*)(sm + SM_INV))[wq * 16 + trow + 8];
        float* vo0 = outV + ((size_t)(b * NL + i_r0) * NH + h) * NE;
        float* vo1 = outV + ((size_t)(b * NL + i_r1) * NH + h) * NE;
        #pragma unroll
        for (int bn = 0; bn < 8; bn++) {
            int e0 = bn * 8 + 2 * c2;
            float o0 = oacc[bn][0] + src[bn * 4 + 0];
            float o1 = oacc[bn][1] + src[bn * 4 + 1];
            float o2 = oacc[bn][2] + src[bn * 4 + 2];
            float o3 = oacc[bn][3] + src[bn * 4 + 3];
            *(float2*)(vo0 + e0) = make_float2(o0 * inv0, o1 * inv0);
            *(float2*)(vo1 + e0) = make_float2(o2 * inv1, o3 * inv1);
        }
    }
    const float ls0 = ((const float*)(sm + SM_LSR))[wq * 16 + trow];
    const float ls1 = ((const float*)(sm + SM_LSR))[wq * 16 + trow + 8];

    const float4 z4 = make_float4(0, 0, 0, 0);

    // ---- column tail zero-fill: 8 rows per warp ----
    {
        const int nk16 = nk * 16;
        #pragma unroll 1
        for (int rr = 0; rr < 8; rr++) {
            const int row = i0 + w * 8 + rr;
            float4* Ar = (float4*)(outA + ((size_t)bh * NL + row) * NS);
            for (int c4 = nk16 + lane; c4 < NS / 4; c4 += 32)
                Ar[c4] = z4;
        }
    }

    // ---- rebuild Q-lo fragments ----
    uint32_t ql[4][4];
    {
        const float* q0 = q + ((size_t)(b * NL + i_r0) * NH + h) * NE;
        const float* q1 = q + ((size_t)(b * NL + i_r1) * NH + h) * NE;
        #pragma unroll
        for (int kc = 0; kc < 4; kc++) {
            int e = kc * 16 + 2 * c2;
            float2 a0 = *(const float2*)(q0 + e);
            float2 a1 = *(const float2*)(q1 + e);
            float2 b0 = *(const float2*)(q0 + e + 8);
            float2 b1 = *(const float2*)(q1 + e + 8);
            float2 f0 = unpack_f16x2(qh[kc][0]);
            float2 f1 = unpack_f16x2(qh[kc][1]);
            float2 f2 = unpack_f16x2(qh[kc][2]);
            float2 f3 = unpack_f16x2(qh[kc][3]);
            ql[kc][0] = cvt_f16x2(a0.y * SCALE - f0.y, a0.x * SCALE - f0.x);
            ql[kc][1] = cvt_f16x2(a1.y * SCALE - f1.y, a1.x * SCALE - f1.x);
            ql[kc][2] = cvt_f16x2(b0.y * SCALE - f2.y, b0.x * SCALE - f2.x);
            ql[kc][3] = cvt_f16x2(b1.y * SCALE - f3.y, b1.x * SCALE - f3.x);
        }
    }

    // ================= PASS 2: full-precision QK, write normalized A =================
    __syncthreads();   // oacc-partial reads done; tile region reusable
    stageK(0, 0);
    CPA_COMMIT();

    buf = 0;
    for (int kt = 0; kt < nk; kt++) {
        if (kt + 1 < nk) { stageK(buf ^ 1, kt + 1); CPA_COMMIT(); CPA_WAIT1(); }
        else CPA_WAIT0();
        __syncthreads();

        const int j0 = kt * TN;
        if (j0 <= i_wmax) {
            const char* bufp = sm + buf * 16384;
            const unsigned char* msk = (const unsigned char*)(sm + SM_MSK + buf * 64);

            uint4 hk[4][2];
            #pragma unroll
            for (int bl = 0; bl < 4; bl++) {
                int bn = wh * 4 + bl;
                hk[bl][0] = *(const uint4*)(bufp + bn * 1024 + lane * 16);
                hk[bl][1] = *(const uint4*)(bufp + bn * 1024 + 512 + lane * 16);
            }
            float sacc[4][4];
            #pragma unroll
            for (int bl = 0; bl < 4; bl++) {
                sacc[bl][0] = 0.0f; sacc[bl][1] = 0.0f;
                sacc[bl][2] = 0.0f; sacc[bl][3] = 0.0f;
            }
            #pragma unroll
            for (int bl = 0; bl < 4; bl++) {
                mma16816(sacc[bl], qh[0], hk[bl][0].x, hk[bl][0].y);
                mma16816(sacc[bl], qh[1], hk[bl][0].z, hk[bl][0].w);
                mma16816(sacc[bl], qh[2], hk[bl][1].x, hk[bl][1].y);
                mma16816(sacc[bl], qh[3], hk[bl][1].z, hk[bl][1].w);
            }
            #pragma unroll
            for (int bl = 0; bl < 4; bl++) {
                mma16816(sacc[bl], ql[0], hk[bl][0].x, hk[bl][0].y);
                mma16816(sacc[bl], ql[1], hk[bl][0].z, hk[bl][0].w);
                mma16816(sacc[bl], ql[2], hk[bl][1].x, hk[bl][1].y);
                mma16816(sacc[bl], ql[3], hk[bl][1].z, hk[bl][1].w);
            }

            #pragma unroll
            for (int bl = 0; bl < 4; bl++) {
                int bn = wh * 4 + bl;
                int colb = j0 + bn * 8 + 2 * c2;
                unsigned char m0 = msk[bn * 8 + 2 * c2];
                unsigned char m1 = msk[bn * 8 + 2 * c2 + 1];
                float a00 = (m0 || colb > i_r0) ? 0.0f : __expf(sacc[bl][0] + ls0);
                float a01 = (m1 || colb + 1 > i_r0) ? 0.0f : __expf(sacc[bl][1] + ls0);
                float a10 = (m0 || colb > i_r1) ? 0.0f : __expf(sacc[bl][2] + ls1);
                float a11 = (m1 || colb + 1 > i_r1) ? 0.0f : __expf(sacc[bl][3] + ls1);
                *(float2*)(Arow0 + colb) = make_float2(a00, a01);
                *(float2*)(Arow1 + colb) = make_float2(a10, a11);
            }
        } else {
            // above-diagonal warp tile: zeros on this warp's 32-col half
            #pragma unroll
            for (int rr = 0; rr < 2; rr++) {
                float* Ar = (rr == 0 ? Arow0 : Arow1) + j0;
                #pragma unroll
                for (int u = 0; u < 2; u++)
                    ((float4*)Ar)[wh * 8 + c2 * 2 + u] = z4;
            }
        }
        buf ^= 1;
        __syncthreads();
    }
}

extern "C" void kernel_launch(void* const* d_in, const int* in_sizes, int n_in,
                              void* d_out, int out_size) {
    const float* q = (const float*)d_in[0];
    const float* k = (const float*)d_in[1];
    const float* v = (const float*)d_in[2];
    const void* mk = d_in[3];
    const void* mq = d_in[4];

    float* outV = (float*)d_out;
    float* outA = outV + (size_t)NB * NL * NH * NE;
    float* outE = outA + (size_t)NB * NH * NL * NS;

    cudaFuncSetAttribute(attn_mma_kernel,
                         cudaFuncAttributeMaxDynamicSharedMemorySize, SM_BYTES);

    prep_kernel<<<2064, 256>>>(k, v, mk, mq);
    attn_mma_kernel<<<NBH * NQT, THREADS, SM_BYTES>>>(q, outV, outA, outE);
}

// round 14
// speedup vs baseline: 1.2936x; 1.1191x over previous
#include <cuda_runtime.h>
#include <cuda_fp16.h>
#include <math.h>
#include <stdint.h>

#define NB 2
#define NL 2048
#define NS 2048
#define NH 8
#define NE 64
#define NBH 16
#define SCALE 0.125f
#define TQ 128
#define TN 64
#define NQT (NL / TQ)
#define NKT (NS / TN)

// ---------------- device scratch (single fp16 tiles) ----------------
__device__ __align__(16) uint8_t g_kf[NBH][NKT][8192];
__device__ __align__(16) uint8_t g_vf[NBH][NKT][8192];
__device__ unsigned char g_mk[NB * NS];
__device__ unsigned char g_mq[NB * NL];

// ---------------- helpers ----------------
__device__ __forceinline__ uint32_t cvt_f16x2(float hi, float lo) {
    uint32_t r;
    asm("cvt.rn.f16x2.f32 %0, %1, %2;" : "=r"(r) : "f"(hi), "f"(lo));
    return r;
}
__device__ __forceinline__ uint32_t smem_u32(const void* p) {
    uint32_t a;
    asm("{ .reg .u64 t; cvta.to.shared.u64 t, %1; cvt.u32.u64 %0, t; }" : "=r"(a) : "l"(p));
    return a;
}
__device__ __forceinline__ void mma16816(float d[4], const uint32_t a[4],
                                         uint32_t b0, uint32_t b1) {
    asm volatile(
        "mma.sync.aligned.m16n8k16.row.col.f32.f16.f16.f32 "
        "{%0,%1,%2,%3},{%4,%5,%6,%7},{%8,%9},{%0,%1,%2,%3};"
        : "+f"(d[0]), "+f"(d[1]), "+f"(d[2]), "+f"(d[3])
        : "r"(a[0]), "r"(a[1]), "r"(a[2]), "r"(a[3]), "r"(b0), "r"(b1));
}
__device__ __forceinline__ void cpa16(uint32_t dst, const void* src) {
    asm volatile("cp.async.cg.shared.global [%0], [%1], 16;" :: "r"(dst), "l"(src));
}
#define CPA_COMMIT() asm volatile("cp.async.commit_group;" ::: "memory")
#define CPA_WAIT0()  asm volatile("cp.async.wait_group 0;" ::: "memory")
#define CPA_WAIT1()  asm volatile("cp.async.wait_group 1;" ::: "memory")

// ---------------- prep: fp16 fragment tiles + mask normalization ----------------
__global__ __launch_bounds__(256) void prep_kernel(const float* __restrict__ k,
                                                   const float* __restrict__ v,
                                                   const void* mk_raw,
                                                   const void* mq_raw) {
    if (blockIdx.x >= 2048) {
        __shared__ int sh_f32, sh_u8;
        if (threadIdx.x == 0) { sh_f32 = 0; sh_u8 = 0; }
        __syncthreads();
        const uint32_t* p32 = (const uint32_t*)mk_raw;
        int f32 = 0, u8 = 0;
        #pragma unroll
        for (int it = 0; it < 4; it++) {
            uint32_t wv = p32[it * 256 + threadIdx.x];
            if (((wv >> 24) & 0xff) == 0x3f) f32 = 1;
            if (wv & 0x00ffff00u) u8 = 1;
        }
        if (f32) atomicOr(&sh_f32, 1);
        if (u8) atomicOr(&sh_u8, 1);
        __syncthreads();
        int mode = sh_f32 ? 2 : (sh_u8 ? 1 : 0);
        int idx = (blockIdx.x - 2048) * 256 + threadIdx.x;
        unsigned char vk, vq;
        if (mode == 2) { vk = ((const float*)mk_raw)[idx] != 0.0f; vq = ((const float*)mq_raw)[idx] != 0.0f; }
        else if (mode == 1) { vk = ((const unsigned char*)mk_raw)[idx] != 0; vq = ((const unsigned char*)mq_raw)[idx] != 0; }
        else { vk = ((const int*)mk_raw)[idx] != 0; vq = ((const int*)mq_raw)[idx] != 0; }
        g_mk[idx] = vk;
        g_mq[idx] = vq;
        return;
    }

    const int kind = blockIdx.x >> 10;                   // 0 = K, 1 = V^T
    const int c = ((blockIdx.x & 1023) << 8) + threadIdx.x;
    const int lane = c & 31;
    const int chunk = (c >> 5) & 1;
    const int bn = (c >> 6) & 7;
    const int kt = (c >> 9) & 31;
    const int bh = c >> 14;
    const int b = bh >> 3, h = bh & 7;
    const int c2 = lane & 3, trow = lane >> 2;

    uint32_t hp[4];
    if (kind == 0) {
        const int j = kt * 64 + bn * 8 + trow;
        const float* base = k + ((size_t)(b * NS + j) * NH + h) * NE;
        #pragma unroll
        for (int kc_in = 0; kc_in < 2; kc_in++) {
            #pragma unroll
            for (int kh = 0; kh < 2; kh++) {
                int e = (chunk * 2 + kc_in) * 16 + kh * 8 + 2 * c2;
                float2 x = *(const float2*)(base + e);
                hp[kc_in * 2 + kh] = cvt_f16x2(x.y, x.x);
            }
        }
        uint32_t off = bn * 1024 + chunk * 512 + lane * 16;
        *(uint4*)(&g_kf[bh][kt][off]) = make_uint4(hp[0], hp[1], hp[2], hp[3]);
    } else {
        const int e = bn * 8 + trow;
        #pragma unroll
        for (int kc_in = 0; kc_in < 2; kc_in++) {
            #pragma unroll
            for (int kh = 0; kh < 2; kh++) {
                int jb = kt * 64 + (chunk * 2 + kc_in) * 16 + kh * 8 + 2 * c2;
                float x0 = v[((size_t)(b * NS + jb) * NH + h) * NE + e];
                float x1 = v[((size_t)(b * NS + jb + 1) * NH + h) * NE + e];
                hp[kc_in * 2 + kh] = cvt_f16x2(x1, x0);
            }
        }
        uint32_t off = bn * 1024 + chunk * 512 + lane * 16;
        *(uint4*)(&g_vf[bh][kt][off]) = make_uint4(hp[0], hp[1], hp[2], hp[3]);
    }
}

// ---------------- attention: 2-pass fp16 flash (consistent Qhi-only scores) ----------------
#define SM_BYTES (32768 + 256)

__global__ __launch_bounds__(256, 1) void attn_mma_kernel(const float* __restrict__ q,
                                                          float* __restrict__ outV,
                                                          float* __restrict__ outA,
                                                          float* __restrict__ outE) {
    extern __shared__ __align__(16) char sm[];
    const int tid = threadIdx.x;
    const int w = tid >> 5;
    const int lane = tid & 31;
    const int c2 = lane & 3, trow = lane >> 2;

    const int qt = (NQT - 1) - (blockIdx.x >> 4);
    const int bh = blockIdx.x & 15;
    const int b = bh >> 3, h = bh & 7;
    const int i0 = qt * TQ;
    const int nk = 2 * qt + 2;

    const int i_r0 = i0 + w * 16 + trow;
    const int i_r1 = i_r0 + 8;
    const int i_wmax = i0 + w * 16 + 15;

    const uint32_t smb = smem_u32(sm);

    // Q-hi fragments (SCALE pre-folded, exact: power-of-2). No lo pass anywhere:
    // both passes compute IDENTICAL s, so row-common fp16 score error cancels in
    // A = exp(s)/l.
    uint32_t qh[4][4];
    {
        const float* q0 = q + ((size_t)(b * NL + i_r0) * NH + h) * NE;
        const float* q1 = q + ((size_t)(b * NL + i_r1) * NH + h) * NE;
        #pragma unroll
        for (int kc = 0; kc < 4; kc++) {
            int e = kc * 16 + 2 * c2;
            float2 a0 = *(const float2*)(q0 + e);
            float2 a1 = *(const float2*)(q1 + e);
            float2 b0 = *(const float2*)(q0 + e + 8);
            float2 b1 = *(const float2*)(q1 + e + 8);
            qh[kc][0] = cvt_f16x2(a0.y * SCALE, a0.x * SCALE);
            qh[kc][1] = cvt_f16x2(a1.y * SCALE, a1.x * SCALE);
            qh[kc][2] = cvt_f16x2(b0.y * SCALE, b0.x * SCALE);
            qh[kc][3] = cvt_f16x2(b1.y * SCALE, b1.x * SCALE);
        }
    }

    float oacc[8][4];
    #pragma unroll
    for (int bn = 0; bn < 8; bn++)
        #pragma unroll
        for (int u = 0; u < 4; u++) oacc[bn][u] = 0.0f;

    float lsum0 = 0.0f, lsum1 = 0.0f, esum0 = 0.0f, esum1 = 0.0f;
    float* Arow0 = outA + ((size_t)bh * NL + i_r0) * NS;
    float* Arow1 = outA + ((size_t)bh * NL + i_r1) * NS;

    auto stageKV = [&](int bufid, int kt) {
        const char* srcK = (const char*)g_kf[bh][kt];
        const char* srcV = (const char*)g_vf[bh][kt];
        uint32_t dst = smb + bufid * 16384;
        #pragma unroll
        for (int i = 0; i < 2; i++) {
            uint32_t off = (uint32_t)(i * 256 + tid) * 16;
            cpa16(dst + off, srcK + off);
            cpa16(dst + 8192 + off, srcV + off);
        }
        if (tid < 16)
            *(uint32_t*)(sm + 32768 + bufid * 64 + tid * 4) =
                *(const uint32_t*)(g_mk + b * NS + kt * 64 + tid * 4);
    };
    auto stageK = [&](int bufid, int kt) {
        const char* srcK = (const char*)g_kf[bh][kt];
        uint32_t dst = smb + bufid * 16384;
        #pragma unroll
        for (int i = 0; i < 2; i++) {
            uint32_t off = (uint32_t)(i * 256 + tid) * 16;
            cpa16(dst + off, srcK + off);
        }
        if (tid < 16)
            *(uint32_t*)(sm + 32768 + bufid * 64 + tid * 4) =
                *(const uint32_t*)(g_mk + b * NS + kt * 64 + tid * 4);
    };

    // ================= PASS 1: lsum/esum + AV (Q-hi only) =================
    stageKV(0, 0);
    CPA_COMMIT();

    int buf = 0;
    for (int kt = 0; kt < nk; kt++) {
        if (kt + 1 < nk) { stageKV(buf ^ 1, kt + 1); CPA_COMMIT(); CPA_WAIT1(); }
        else CPA_WAIT0();
        __syncthreads();

        const int j0 = kt * TN;
        if (j0 <= i_wmax) {
            const char* bufp = sm + buf * 16384;
            const unsigned char* msk = (const unsigned char*)(sm + 32768 + buf * 64);

            // ---- QK + epilogue, 8 independent bn chains ----
            uint32_t pa_hi[4][4];
            #pragma unroll
            for (int bn = 0; bn < 8; bn++) {
                uint4 h0 = *(const uint4*)(bufp + bn * 1024 + lane * 16);
                uint4 h1 = *(const uint4*)(bufp + bn * 1024 + 512 + lane * 16);
                float sacc[4] = {0.0f, 0.0f, 0.0f, 0.0f};
                mma16816(sacc, qh[0], h0.x, h0.y);
                mma16816(sacc, qh[1], h0.z, h0.w);
                mma16816(sacc, qh[2], h1.x, h1.y);
                mma16816(sacc, qh[3], h1.z, h1.w);

                int colb = j0 + bn * 8 + 2 * c2;
                unsigned char m0 = msk[bn * 8 + 2 * c2];
                unsigned char m1 = msk[bn * 8 + 2 * c2 + 1];
                float e00 = (m0 || colb > i_r0) ? 0.0f : __expf(sacc[0]);
                float e01 = (m1 || colb + 1 > i_r0) ? 0.0f : __expf(sacc[1]);
                float e10 = (m0 || colb > i_r1) ? 0.0f : __expf(sacc[2]);
                float e11 = (m1 || colb + 1 > i_r1) ? 0.0f : __expf(sacc[3]);
                lsum0 += e00 + e01; esum0 += e00 * sacc[0] + e01 * sacc[1];
                lsum1 += e10 + e11; esum1 += e10 * sacc[2] + e11 * sacc[3];
                int kc = bn >> 1, s0i = (bn & 1) * 2;
                pa_hi[kc][s0i + 0] = cvt_f16x2(e01, e00);
                pa_hi[kc][s0i + 1] = cvt_f16x2(e11, e10);
            }

            // ---- AV: single-pass (Phi) ----
            #pragma unroll
            for (int bn = 0; bn < 8; bn++) {
                uint4 h0 = *(const uint4*)(bufp + 8192 + bn * 1024 + lane * 16);
                uint4 h1 = *(const uint4*)(bufp + 8192 + bn * 1024 + 512 + lane * 16);
                mma16816(oacc[bn], pa_hi[0], h0.x, h0.y);
                mma16816(oacc[bn], pa_hi[1], h0.z, h0.w);
                mma16816(oacc[bn], pa_hi[2], h1.x, h1.y);
                mma16816(oacc[bn], pa_hi[3], h1.z, h1.w);
            }
        }
        buf ^= 1;
        __syncthreads();
    }

    // ---- stats: quad reduce, V write, entropy ----
    lsum0 += __shfl_xor_sync(0xffffffffu, lsum0, 1);
    lsum0 += __shfl_xor_sync(0xffffffffu, lsum0, 2);
    lsum1 += __shfl_xor_sync(0xffffffffu, lsum1, 1);
    lsum1 += __shfl_xor_sync(0xffffffffu, lsum1, 2);
    esum0 += __shfl_xor_sync(0xffffffffu, esum0, 1);
    esum0 += __shfl_xor_sync(0xffffffffu, esum0, 2);
    esum1 += __shfl_xor_sync(0xffffffffu, esum1, 1);
    esum1 += __shfl_xor_sync(0xffffffffu, esum1, 2);

    const bool mq0 = g_mq[b * NL + i_r0] != 0;
    const bool mq1 = g_mq[b * NL + i_r1] != 0;
    const float inv0 = mq0 ? 0.0f : 1.0f / lsum0;
    const float inv1 = mq1 ? 0.0f : 1.0f / lsum1;
    const float ls0 = __logf(inv0);     // -inf if masked -> exp() = 0
    const float ls1 = __logf(inv1);

    {
        float* vo0 = outV + ((size_t)(b * NL + i_r0) * NH + h) * NE;
        float* vo1 = outV + ((size_t)(b * NL + i_r1) * NH + h) * NE;
        #pragma unroll
        for (int bn = 0; bn < 8; bn++) {
            int e0 = bn * 8 + 2 * c2;
            *(float2*)(vo0 + e0) = make_float2(oacc[bn][0] * inv0, oacc[bn][1] * inv0);
            *(float2*)(vo1 + e0) = make_float2(oacc[bn][2] * inv1, oacc[bn][3] * inv1);
        }
    }
    if (c2 == 0) {
        outE[bh * NL + i_r0] = mq0 ? 0.0f : (__logf(lsum0) - esum0 / lsum0);
        outE[bh * NL + i_r1] = mq1 ? 0.0f : (__logf(lsum1) - esum1 / lsum1);
    }

    const float4 z4 = make_float4(0, 0, 0, 0);

    // ---- column tail zero-fill (j >= nk*64) ----
    {
        const int nk16 = nk * 16;
        #pragma unroll 1
        for (int rr = 0; rr < 16; rr++) {
            const int row = i0 + w * 16 + rr;
            float4* Ar = (float4*)(outA + ((size_t)bh * NL + row) * NS);
            for (int c4 = nk16 + lane; c4 < NS / 4; c4 += 32)
                Ar[c4] = z4;
        }
    }

    // ================= PASS 2: identical Qhi-only scores, write normalized A =================
    __syncthreads();
    stageK(0, 0);
    CPA_COMMIT();

    buf = 0;
    for (int kt = 0; kt < nk; kt++) {
        if (kt + 1 < nk) { stageK(buf ^ 1, kt + 1); CPA_COMMIT(); CPA_WAIT1(); }
        else CPA_WAIT0();
        __syncthreads();

        const int j0 = kt * TN;
        if (j0 <= i_wmax) {
            const char* bufp = sm + buf * 16384;
            const unsigned char* msk = (const unsigned char*)(sm + 32768 + buf * 64);

            #pragma unroll
            for (int bn = 0; bn < 8; bn++) {
                uint4 h0 = *(const uint4*)(bufp + bn * 1024 + lane * 16);
                uint4 h1 = *(const uint4*)(bufp + bn * 1024 + 512 + lane * 16);
                float sacc[4] = {0.0f, 0.0f, 0.0f, 0.0f};
                mma16816(sacc, qh[0], h0.x, h0.y);
                mma16816(sacc, qh[1], h0.z, h0.w);
                mma16816(sacc, qh[2], h1.x, h1.y);
                mma16816(sacc, qh[3], h1.z, h1.w);

                int colb = j0 + bn * 8 + 2 * c2;
                unsigned char m0 = msk[bn * 8 + 2 * c2];
                unsigned char m1 = msk[bn * 8 + 2 * c2 + 1];
                float a00 = (m0 || colb > i_r0) ? 0.0f : __expf(sacc[0] + ls0);
                float a01 = (m1 || colb + 1 > i_r0) ? 0.0f : __expf(sacc[1] + ls0);
                float a10 = (m0 || colb > i_r1) ? 0.0f : __expf(sacc[2] + ls1);
                float a11 = (m1 || colb + 1 > i_r1) ? 0.0f : __expf(sacc[3] + ls1);
                *(float2*)(Arow0 + colb) = make_float2(a00, a01);
                *(float2*)(Arow1 + colb) = make_float2(a10, a11);
            }
        } else {
            // above-diagonal warp tile: zeros
            #pragma unroll
            for (int rr = 0; rr < 2; rr++) {
                float* Ar = (rr == 0 ? Arow0 : Arow1) + j0;
                #pragma unroll
                for (int u = 0; u < 4; u++)
                    ((float4*)Ar)[c2 * 4 + u] = z4;
            }
        }
        buf ^= 1;
        __syncthreads();
    }
}

extern "C" void kernel_launch(void* const* d_in, const int* in_sizes, int n_in,
                              void* d_out, int out_size) {
    const float* q = (const float*)d_in[0];
    const float* k = (const float*)d_in[1];
    const float* v = (const float*)d_in[2];
    const void* mk = d_in[3];
    const void* mq = d_in[4];

    float* outV = (float*)d_out;
    float* outA = outV + (size_t)NB * NL * NH * NE;
    float* outE = outA + (size_t)NB * NH * NL * NS;

    cudaFuncSetAttribute(attn_mma_kernel,
                         cudaFuncAttributeMaxDynamicSharedMemorySize, SM_BYTES);

    prep_kernel<<<2064, 256>>>(k, v, mk, mq);
    attn_mma_kernel<<<NBH * NQT, 256, SM_BYTES>>>(q, outV, outA, outE);
}